// round 5
// baseline (speedup 1.0000x reference)
#include <cuda_runtime.h>
#include <stdint.h>

#define NPROT 4096
#define IN_F  512
#define HALF  256
#define F     64
#define NW    128
#define ALPHA 0.2f

// ---------------- scratch (device globals; no allocation allowed) ----------
__device__ float    g_Wh1[NPROT * F];
__device__ float    g_Wh2[NPROT * F];
__device__ float    g_s1a[NPROT], g_s2a[NPROT];   // hop1 row/col scores
__device__ float    g_s1b[NPROT], g_s2b[NPROT];   // hop2
__device__ unsigned g_bits1[NPROT * NW];
__device__ float    g_hp[NPROT * 2 * F];
__device__ float    g_bnsum[2 * F], g_bnsq[2 * F];

// ============ fused GEMM: Wh = h @ blockdiag(W1,W2), + score vectors ========
// BM=32 rows, BN=128 cols (cols 0-63 = Wh1 from h[:,0:256], 64-127 = Wh2 from
// h[:,256:512]), BK=16, 256 threads, 4x4 micro-tile. 128 blocks.
__global__ __launch_bounds__(256) void k_wh(const float* __restrict__ h,
                                            const float* __restrict__ W1,
                                            const float* __restrict__ W2,
                                            const float* __restrict__ a)
{
    __shared__ __align__(16) float hsT[2][16][32];   // [half][k][row]
    __shared__ __align__(16) float Ws[16][128];      // [k][col]

    int t = threadIdx.x;
    int rowBase = blockIdx.x * 32;
    int cx = t & 31, ry = t >> 5;          // warp == ry; lane == cx
    int half = (cx >= 16);
    int r0 = ry * 4;

    float acc[4][4] = {};

    // tile-load index precompute
    int lh = t >> 7, lt = t & 127;
    int lrow = lt >> 2, lk4 = (lt & 3) * 4;
    int wkk = t >> 4, wc8 = (t & 15) * 8;

    for (int k0 = 0; k0 < HALF; k0 += 16) {
        // h tile: both halves, transposed into smem
        float4 hv = *(const float4*)&h[(rowBase + lrow) * IN_F + lh * HALF + k0 + lk4];
        hsT[lh][lk4 + 0][lrow] = hv.x;
        hsT[lh][lk4 + 1][lrow] = hv.y;
        hsT[lh][lk4 + 2][lrow] = hv.z;
        hsT[lh][lk4 + 3][lrow] = hv.w;
        // W tile (block-diagonal view)
        const float* Wsrc = (wc8 < 64) ? &W1[(k0 + wkk) * F + wc8]
                                       : &W2[(k0 + wkk) * F + (wc8 - 64)];
        float4 w0 = *(const float4*)Wsrc;
        float4 w1 = *(const float4*)(Wsrc + 4);
        *(float4*)&Ws[wkk][wc8]     = w0;
        *(float4*)&Ws[wkk][wc8 + 4] = w1;
        __syncthreads();
#pragma unroll
        for (int kk = 0; kk < 16; kk++) {
            float4 av = *(const float4*)&hsT[half][kk][r0];
            float4 bv = *(const float4*)&Ws[kk][cx * 4];
            float ar[4] = {av.x, av.y, av.z, av.w};
            float br[4] = {bv.x, bv.y, bv.z, bv.w};
#pragma unroll
            for (int r = 0; r < 4; r++)
#pragma unroll
                for (int j = 0; j < 4; j++)
                    acc[r][j] = fmaf(ar[r], br[j], acc[r][j]);
        }
        __syncthreads();
    }

    // write Wh (float4, coalesced)
    float* dst = half ? g_Wh2 : g_Wh1;
    int col = half ? (cx - 16) * 4 : cx * 4;     // local column within the half
#pragma unroll
    for (int r = 0; r < 4; r++) {
        float4 v = make_float4(acc[r][0], acc[r][1], acc[r][2], acc[r][3]);
        *(float4*)&dst[(rowBase + r0 + r) * F + col] = v;
    }

    // fused score vectors: s1 = Wh@a[0:64], s2 = Wh@a[64:128] (same a both hops)
    float a1[4], a2[4];
#pragma unroll
    for (int j = 0; j < 4; j++) { a1[j] = a[col + j]; a2[j] = a[64 + col + j]; }
#pragma unroll
    for (int r = 0; r < 4; r++) {
        float p1 = 0.f, p2 = 0.f;
#pragma unroll
        for (int j = 0; j < 4; j++) {
            p1 = fmaf(acc[r][j], a1[j], p1);
            p2 = fmaf(acc[r][j], a2[j], p2);
        }
#pragma unroll
        for (int o = 8; o; o >>= 1) {    // reduces within each 16-lane half
            p1 += __shfl_xor_sync(0xffffffffu, p1, o);
            p2 += __shfl_xor_sync(0xffffffffu, p2, o);
        }
        int row = rowBase + r0 + r;
        if (cx == 0)  { g_s1a[row] = p1; g_s2a[row] = p2; }
        if (cx == 16) { g_s1b[row] = p1; g_s2b[row] = p2; }
    }

    // zero BN accumulators (any block of this kernel; all done before attn)
    if (blockIdx.x == 0 && t < 2 * F) { g_bnsum[t] = 0.f; g_bnsq[t] = 0.f; }
}

// ============ shared helpers =================================================
// Deterministic neighbor-list build from 128 bit-words via prefix scan.
__device__ __forceinline__ int build_nbr(const unsigned* __restrict__ bits,
                                         unsigned short* nbr, int* wsum,
                                         int t, int lane, int warp)
{
    int n = (t < NW) ? __popc(bits[t]) : 0;
    int sc = n;
#pragma unroll
    for (int o = 1; o < 32; o <<= 1) {
        int v = __shfl_up_sync(0xffffffffu, sc, o);
        if (lane >= o) sc += v;
    }
    if (lane == 31) wsum[warp] = sc;
    __syncthreads();
    int wbase = 0;
#pragma unroll
    for (int w = 0; w < 8; w++) if (w < warp) wbase += wsum[w];
    int base = wbase + sc - n;                 // exclusive offset
    if (t < NW) {
        unsigned m = bits[t];
        int b = base;
        while (m) { int bit = __ffs(m) - 1; m &= m - 1; nbr[b++] = (unsigned short)(t * 32 + bit); }
    }
    int deg = 0;
#pragma unroll
    for (int w = 0; w < 8; w++) deg += wsum[w];
    __syncthreads();
    return deg;
}

// cold path: degree-0 row -> uniform softmax == column mean (never expected)
__device__ void colmean_fallback(int i, int t, const float* __restrict__ Wh, int colOff)
{
    if (t < F) {
        float s = 0.f;
        for (int r = 0; r < NPROT; r++) s += Wh[r * F + t];
        float v = s * (1.f / NPROT);
        g_hp[i * 128 + colOff + t] = v;
        atomicAdd(&g_bnsum[colOff + t], v);
        atomicAdd(&g_bnsq[colOff + t], v * v);
    }
}

// sparse masked softmax + aggregate for one row. e-values cached in smem
// between the max pass and the weighted pass. 8 groups of 32, float2 gathers.
__device__ __forceinline__ void attn_aggregate(
    int i, int t, int deg,
    const unsigned short* __restrict__ nbr, float* ecache,
    float* red, float* dsh,
    float s1i, const float* __restrict__ s2,
    const float* __restrict__ Wh, int colOff)
{
    float m = -3.4e38f;
    for (int k = t; k < deg; k += 256) {
        float e = s1i + s2[nbr[k]];
        e = (e > 0.f) ? e : ALPHA * e;
        ecache[k] = e;
        m = fmaxf(m, e);
    }
    red[t] = m;
    __syncthreads();
#pragma unroll
    for (int s = 128; s > 0; s >>= 1) {
        if (t < s) red[t] = fmaxf(red[t], red[t + s]);
        __syncthreads();
    }
    m = red[0];
    __syncthreads();

    int g = t >> 5, lane = t & 31;
    float2 num = make_float2(0.f, 0.f);
    float den = 0.f;
    const float2* Whv = (const float2*)Wh;
#pragma unroll 2
    for (int k = g; k < deg; k += 8) {
        float wv = __expf(ecache[k] - m);
        den += wv;
        float2 w2 = Whv[(int)nbr[k] * 32 + lane];
        num.x = fmaf(wv, w2.x, num.x);
        num.y = fmaf(wv, w2.y, num.y);
    }
    float2* red2 = (float2*)red;   // red has 512 floats
    red2[t] = num;
    if (lane == 0) dsh[g] = den;
    __syncthreads();
    if (t < 32) {
        float sx = 0.f, sy = 0.f, dtot = 0.f;
#pragma unroll
        for (int g2 = 0; g2 < 8; g2++) {
            float2 v = red2[g2 * 32 + t];
            sx += v.x; sy += v.y;
            dtot += dsh[g2];
        }
        float inv = 1.f / dtot;
        float v0 = sx * inv, v1 = sy * inv;
        int c = colOff + 2 * t;
        g_hp[i * 128 + c]     = v0;
        g_hp[i * 128 + c + 1] = v1;
        atomicAdd(&g_bnsum[c],     v0); atomicAdd(&g_bnsq[c],     v0 * v0);
        atomicAdd(&g_bnsum[c + 1], v1); atomicAdd(&g_bnsq[c + 1], v1 * v1);
    }
}

// ============ kernel 2: pack adj row + hop-1 attention =======================
__global__ __launch_bounds__(256) void k_packattn1(const float* __restrict__ adj)
{
    __shared__ unsigned       sbits[NW];
    __shared__ unsigned short nbr[NPROT];
    __shared__ float          ecache[NPROT];
    __shared__ float          red[512];
    __shared__ float          dsh[8];
    __shared__ int            wsum[8];

    int i = blockIdx.x, t = threadIdx.x;
    int lane = t & 31, warp = t >> 5;

    // pack: 16 fully-coalesced 1KB loads + ballot
    const float* arow = adj + (size_t)i * NPROT;
#pragma unroll
    for (int w = 0; w < 16; w++) {
        unsigned m = __ballot_sync(0xffffffffu, arow[w * 256 + t] > 0.f);
        if (lane == 0) {
            sbits[w * 8 + warp] = m;
            g_bits1[i * NW + w * 8 + warp] = m;
        }
    }
    __syncthreads();

    int deg = build_nbr(sbits, nbr, wsum, t, lane, warp);
    if (deg == 0) { colmean_fallback(i, t, g_Wh1, 0); return; }

    attn_aggregate(i, t, deg, nbr, ecache, red, dsh, g_s1a[i], g_s2a, g_Wh1, 0);
}

// ============ kernel 3: boolean adj^2 (smem only) + hop-2 attention ==========
__global__ __launch_bounds__(256) void k_adj2attn2()
{
    __shared__ unsigned       sbits[NW];
    __shared__ unsigned       bits2[NW];
    __shared__ unsigned short nbr[NPROT];
    __shared__ float          ecache[NPROT];
    __shared__ float          red[512];
    __shared__ float          dsh[8];
    __shared__ int            wsum[8];

    int i = blockIdx.x, t = threadIdx.x;
    int lane = t & 31, warp = t >> 5;

    if (t < NW) { sbits[t] = g_bits1[i * NW + t]; bits2[t] = 0u; }
    __syncthreads();

    int deg1 = build_nbr(sbits, nbr, wsum, t, lane, warp);

    // bits2 row i = OR of neighbor rows (two half-threads per word)
    {
        int word = t & 127, hh = t >> 7;
        unsigned acc = 0u;
#pragma unroll 2
        for (int k = hh; k < deg1; k += 2)
            acc |= g_bits1[(int)nbr[k] * NW + word];
        if (acc) atomicOr(&bits2[word], acc);
    }
    __syncthreads();
    if (t == 0) bits2[i >> 5] &= ~(1u << (i & 31));   // zero diagonal of adj2
    __syncthreads();

    int deg2 = build_nbr(bits2, nbr, wsum, t, lane, warp);
    if (deg2 == 0) { colmean_fallback(i, t, g_Wh2, 64); return; }

    attn_aggregate(i, t, deg2, nbr, ecache, red, dsh, g_s1b[i], g_s2b, g_Wh2, 64);
}

// ============ kernel 4: batchnorm (stats inline from atomics) + leakyrelu ====
__global__ void k_bnapply(const float* __restrict__ gamma,
                          const float* __restrict__ beta,
                          float* __restrict__ out)
{
    int idx = blockIdx.x * blockDim.x + threadIdx.x;   // NPROT*128 elements
    int c = idx & 127;
    float mean = g_bnsum[c] * (1.f / NPROT);
    float var  = g_bnsq[c] * (1.f / NPROT) - mean * mean;
    float rstd = rsqrtf(var + 1e-5f);
    float v = g_hp[idx];
    float o = gamma[c] * (v - mean) * rstd + beta[c];
    out[idx] = (o > 0.f) ? o : ALPHA * o;
}

// ============ launch ==========================================================
extern "C" void kernel_launch(void* const* d_in, const int* in_sizes, int n_in,
                              void* d_out, int out_size)
{
    const float* h     = (const float*)d_in[0];
    const float* adj   = (const float*)d_in[1];
    const float* W1    = (const float*)d_in[2];
    const float* W2    = (const float*)d_in[3];
    const float* a     = (const float*)d_in[4];
    const float* gamma = (const float*)d_in[5];
    const float* beta  = (const float*)d_in[6];
    float* out = (float*)d_out;

    k_wh        <<<NPROT / 32, 256>>>(h, W1, W2, a);
    k_packattn1 <<<NPROT, 256>>>(adj);
    k_adj2attn2 <<<NPROT, 256>>>();
    k_bnapply   <<<(NPROT * 128) / 256, 256>>>(gamma, beta, out);
}

// round 6
// speedup vs baseline: 1.7798x; 1.7798x over previous
#include <cuda_runtime.h>
#include <stdint.h>

#define NPROT 4096
#define IN_F  512
#define HALF  256
#define F     64
#define NW    128
#define ALPHA 0.2f

typedef unsigned long long ull;

// ---------------- scratch (device globals; no allocation allowed) ----------
__device__ float    g_Wh1[NPROT * F];
__device__ float    g_Wh2[NPROT * F];
__device__ float    g_s1a[NPROT], g_s2a[NPROT];   // hop1 row/col scores
__device__ float    g_s1b[NPROT], g_s2b[NPROT];   // hop2
__device__ unsigned g_bits1[NPROT * NW];
__device__ float    g_hp[NPROT * 2 * F];
__device__ float    g_bnsum[2 * F], g_bnsq[2 * F];
__device__ float    g_scale[2 * F], g_shift[2 * F];

// ---------------- packed fp32x2 helpers (sm_103a FFMA2 path) ----------------
__device__ __forceinline__ ull pack2(float lo, float hi) {
    ull r; asm("mov.b64 %0, {%1, %2};" : "=l"(r) : "f"(lo), "f"(hi)); return r;
}
__device__ __forceinline__ void unpack2(ull v, float& lo, float& hi) {
    asm("mov.b64 {%0, %1}, %2;" : "=f"(lo), "=f"(hi) : "l"(v));
}
__device__ __forceinline__ void ffma2(ull& acc, ull a, ull b) {
    asm("fma.rn.f32x2 %0, %1, %2, %0;" : "+l"(acc) : "l"(a), "l"(b));
}

// ============ fused GEMM: Wh = h @ blockdiag(W1,W2), + score vectors ========
// BM=16 rows, BN=128 cols (0-63 = Wh1 from h[:,0:256], 64-127 = Wh2 from
// h[:,256:512]), BK=16, 256 threads, 2x4 micro-tile via f32x2. 256 blocks.
__global__ __launch_bounds__(256) void k_wh(const float* __restrict__ h,
                                            const float* __restrict__ W1,
                                            const float* __restrict__ W2,
                                            const float* __restrict__ a)
{
    __shared__ float hsT[2][16][16];                 // [half][k][row]
    __shared__ __align__(16) float Ws[16][128];      // [k][col]

    int t = threadIdx.x;
    int rowBase = blockIdx.x * 16;
    int cx = t & 31, ry = t >> 5;          // lane = cx, warp = ry
    int half = (cx >= 16);
    int lc = (cx & 15) * 4;                // local column within the half
    int r0 = ry * 2;

    ull acc[2][2] = {};                    // [row][colpair]

    // tile-load index precompute
    int lhalf = t >> 7, lt63 = t & 63;
    int lrow = lt63 >> 2, lk4 = (lt63 & 3) * 4;
    int wkk = t >> 4, wc8 = (t & 15) * 8;

    for (int k0 = 0; k0 < HALF; k0 += 16) {
        if ((t & 127) < 64) {
            float4 hv = *(const float4*)&h[(rowBase + lrow) * IN_F + lhalf * HALF + k0 + lk4];
            hsT[lhalf][lk4 + 0][lrow] = hv.x;
            hsT[lhalf][lk4 + 1][lrow] = hv.y;
            hsT[lhalf][lk4 + 2][lrow] = hv.z;
            hsT[lhalf][lk4 + 3][lrow] = hv.w;
        }
        const float* Wsrc = (wc8 < 64) ? &W1[(k0 + wkk) * F + wc8]
                                       : &W2[(k0 + wkk) * F + (wc8 - 64)];
        *(float4*)&Ws[wkk][wc8]     = *(const float4*)Wsrc;
        *(float4*)&Ws[wkk][wc8 + 4] = *(const float4*)(Wsrc + 4);
        __syncthreads();
#pragma unroll
        for (int kk = 0; kk < 16; kk++) {
            float a0 = hsT[half][kk][r0];
            float a1 = hsT[half][kk][r0 + 1];
            ull A0 = pack2(a0, a0), A1 = pack2(a1, a1);
            ulonglong2 bb = *(const ulonglong2*)&Ws[kk][cx * 4];
            ffma2(acc[0][0], A0, bb.x); ffma2(acc[0][1], A0, bb.y);
            ffma2(acc[1][0], A1, bb.x); ffma2(acc[1][1], A1, bb.y);
        }
        __syncthreads();
    }

    float o[2][4];
    unpack2(acc[0][0], o[0][0], o[0][1]); unpack2(acc[0][1], o[0][2], o[0][3]);
    unpack2(acc[1][0], o[1][0], o[1][1]); unpack2(acc[1][1], o[1][2], o[1][3]);

    float* dst = half ? g_Wh2 : g_Wh1;
#pragma unroll
    for (int r = 0; r < 2; r++)
        *(float4*)&dst[(rowBase + r0 + r) * F + lc] =
            make_float4(o[r][0], o[r][1], o[r][2], o[r][3]);

    // fused score vectors: s1 = Wh@a[0:64], s2 = Wh@a[64:128]
    float a1v[4], a2v[4];
#pragma unroll
    for (int j = 0; j < 4; j++) { a1v[j] = a[lc + j]; a2v[j] = a[64 + lc + j]; }
#pragma unroll
    for (int r = 0; r < 2; r++) {
        float p1 = 0.f, p2 = 0.f;
#pragma unroll
        for (int j = 0; j < 4; j++) {
            p1 = fmaf(o[r][j], a1v[j], p1);
            p2 = fmaf(o[r][j], a2v[j], p2);
        }
#pragma unroll
        for (int os = 8; os; os >>= 1) {   // reduce within each 16-lane half
            p1 += __shfl_xor_sync(0xffffffffu, p1, os);
            p2 += __shfl_xor_sync(0xffffffffu, p2, os);
        }
        int row = rowBase + r0 + r;
        if (cx == 0)  { g_s1a[row] = p1; g_s2a[row] = p2; }
        if (cx == 16) { g_s1b[row] = p1; g_s2b[row] = p2; }
    }

    if (blockIdx.x == 0 && t < 128) { g_bnsum[t] = 0.f; g_bnsq[t] = 0.f; }
}

// ============ shared helpers =================================================
__device__ __forceinline__ int build_nbr(const unsigned* __restrict__ bits,
                                         unsigned short* nbr, int* wsum,
                                         int t, int lane, int warp)
{
    int n = (t < NW) ? __popc(bits[t]) : 0;
    int sc = n;
#pragma unroll
    for (int o = 1; o < 32; o <<= 1) {
        int v = __shfl_up_sync(0xffffffffu, sc, o);
        if (lane >= o) sc += v;
    }
    if (lane == 31) wsum[warp] = sc;
    __syncthreads();
    int wbase = 0;
#pragma unroll
    for (int w = 0; w < 8; w++) if (w < warp) wbase += wsum[w];
    int base = wbase + sc - n;
    if (t < NW) {
        unsigned m = bits[t];
        int b = base;
        while (m) { int bit = __ffs(m) - 1; m &= m - 1; nbr[b++] = (unsigned short)(t * 32 + bit); }
    }
    int deg = 0;
#pragma unroll
    for (int w = 0; w < 8; w++) deg += wsum[w];
    __syncthreads();
    return deg;
}

// cold path: degree-0 row -> uniform softmax == column mean (P ~ 1e-9)
__device__ void colmean_fallback(int i, int t, const float* __restrict__ Wh, int colOff)
{
    if (t < F) {
        float s = 0.f;
        for (int r = 0; r < NPROT; r++) s += Wh[r * F + t];
        g_hp[i * 128 + colOff + t] = s * (1.f / NPROT);
    }
}

// sparse masked softmax + aggregate. 8 groups of 32 lanes, float2 gathers,
// 4-deep software pipeline for MLP.
__device__ __forceinline__ void attn_aggregate(
    int i, int t, int deg, const unsigned short* __restrict__ nbr,
    float* red, float* dsh, float s1i,
    const float* __restrict__ s2, const float* __restrict__ Wh, int colOff)
{
    float m = -3.4e38f;
    for (int k = t; k < deg; k += 256) {
        float e = s1i + s2[nbr[k]];
        e = (e > 0.f) ? e : ALPHA * e;
        m = fmaxf(m, e);
    }
    red[t] = m;
    __syncthreads();
#pragma unroll
    for (int s = 128; s > 0; s >>= 1) {
        if (t < s) red[t] = fmaxf(red[t], red[t + s]);
        __syncthreads();
    }
    m = red[0];
    __syncthreads();

    int g = t >> 5, lane = t & 31;
    const float2* __restrict__ Whv = (const float2*)Wh;
    float2 n0 = {0.f, 0.f}, n1 = {0.f, 0.f}, n2 = {0.f, 0.f}, n3 = {0.f, 0.f};
    float d0 = 0.f, d1 = 0.f, d2 = 0.f, d3 = 0.f;
    int k = g;
    for (; k + 24 < deg; k += 32) {
        int j0 = nbr[k], j1 = nbr[k + 8], j2 = nbr[k + 16], j3 = nbr[k + 24];
        float2 w0 = Whv[j0 * 32 + lane];
        float2 w1 = Whv[j1 * 32 + lane];
        float2 w2 = Whv[j2 * 32 + lane];
        float2 w3 = Whv[j3 * 32 + lane];
        float e0 = s1i + s2[j0]; e0 = (e0 > 0.f) ? e0 : ALPHA * e0;
        float e1 = s1i + s2[j1]; e1 = (e1 > 0.f) ? e1 : ALPHA * e1;
        float e2 = s1i + s2[j2]; e2 = (e2 > 0.f) ? e2 : ALPHA * e2;
        float e3 = s1i + s2[j3]; e3 = (e3 > 0.f) ? e3 : ALPHA * e3;
        float v0 = __expf(e0 - m), v1 = __expf(e1 - m);
        float v2 = __expf(e2 - m), v3 = __expf(e3 - m);
        d0 += v0; n0.x = fmaf(v0, w0.x, n0.x); n0.y = fmaf(v0, w0.y, n0.y);
        d1 += v1; n1.x = fmaf(v1, w1.x, n1.x); n1.y = fmaf(v1, w1.y, n1.y);
        d2 += v2; n2.x = fmaf(v2, w2.x, n2.x); n2.y = fmaf(v2, w2.y, n2.y);
        d3 += v3; n3.x = fmaf(v3, w3.x, n3.x); n3.y = fmaf(v3, w3.y, n3.y);
    }
    for (; k < deg; k += 8) {
        int j = nbr[k];
        float e = s1i + s2[j]; e = (e > 0.f) ? e : ALPHA * e;
        float v = __expf(e - m);
        float2 w = Whv[j * 32 + lane];
        d0 += v; n0.x = fmaf(v, w.x, n0.x); n0.y = fmaf(v, w.y, n0.y);
    }
    float2 num = make_float2(n0.x + n1.x + n2.x + n3.x,
                             n0.y + n1.y + n2.y + n3.y);
    float den = d0 + d1 + d2 + d3;          // identical across lanes of a group
    ((float2*)red)[t] = num;
    if (lane == 0) dsh[g] = den;
    __syncthreads();
    if (t < 32) {
        float sx = 0.f, sy = 0.f, dtot = 0.f;
#pragma unroll
        for (int g2 = 0; g2 < 8; g2++) {
            float2 v = ((float2*)red)[g2 * 32 + t];
            sx += v.x; sy += v.y;
            dtot += dsh[g2];
        }
        float inv = 1.f / dtot;
        int c = colOff + 2 * t;
        g_hp[i * 128 + c]     = sx * inv;
        g_hp[i * 128 + c + 1] = sy * inv;
    }
}

// ============ kernel 2: pack adj row + hop-1 attention =======================
__global__ __launch_bounds__(256) void k_packattn1(const float* __restrict__ adj)
{
    __shared__ unsigned       sbits[NW];
    __shared__ unsigned short nbr[NPROT];
    __shared__ float          red[512];
    __shared__ float          dsh[8];
    __shared__ int            wsum[8];

    int i = blockIdx.x, t = threadIdx.x;
    int lane = t & 31, warp = t >> 5;

    const float* arow = adj + (size_t)i * NPROT;
#pragma unroll
    for (int w = 0; w < 16; w++) {
        unsigned m = __ballot_sync(0xffffffffu, arow[w * 256 + t] > 0.f);
        if (lane == 0) {
            sbits[w * 8 + warp] = m;
            g_bits1[i * NW + w * 8 + warp] = m;
        }
    }
    __syncthreads();

    int deg = build_nbr(sbits, nbr, wsum, t, lane, warp);
    if (deg == 0) { colmean_fallback(i, t, g_Wh1, 0); return; }

    attn_aggregate(i, t, deg, nbr, red, dsh, g_s1a[i], g_s2a, g_Wh1, 0);
}

// ============ kernel 3: boolean adj^2 (smem only) + hop-2 attention ==========
__global__ __launch_bounds__(256) void k_adj2attn2()
{
    __shared__ unsigned       sbits[NW];
    __shared__ unsigned       bits2[NW];
    __shared__ unsigned short nbr[NPROT];
    __shared__ float          red[512];
    __shared__ float          dsh[8];
    __shared__ int            wsum[8];

    int i = blockIdx.x, t = threadIdx.x;
    int lane = t & 31, warp = t >> 5;

    if (t < NW) { sbits[t] = g_bits1[i * NW + t]; bits2[t] = 0u; }
    __syncthreads();

    int deg1 = build_nbr(sbits, nbr, wsum, t, lane, warp);

    // bits2 row i = OR of neighbor rows (two half-blocks per word)
    {
        int word = t & 127, hh = t >> 7;
        unsigned acc = 0u;
        for (int k = hh; k < deg1; k += 2)
            acc |= g_bits1[(int)nbr[k] * NW + word];
        if (acc) atomicOr(&bits2[word], acc);
    }
    __syncthreads();
    if (t == 0) bits2[i >> 5] &= ~(1u << (i & 31));   // zero diagonal of adj2
    __syncthreads();

    int deg2 = build_nbr(bits2, nbr, wsum, t, lane, warp);
    if (deg2 == 0) { colmean_fallback(i, t, g_Wh2, 64); return; }

    attn_aggregate(i, t, deg2, nbr, red, dsh, g_s1b[i], g_s2b, g_Wh2, 64);
}

// ============ kernel 4: BN stats (coalesced, block-partial atomics) ==========
__global__ __launch_bounds__(256) void k_bnstats()
{
    int b = blockIdx.x;                       // 128 blocks x 32 rows
    int c = threadIdx.x & 127, rg = threadIdx.x >> 7;
    int r0 = b * 32 + rg * 16;
    float s = 0.f, q = 0.f;
#pragma unroll
    for (int r = 0; r < 16; r++) {
        float v = g_hp[(r0 + r) * 128 + c];
        s += v; q = fmaf(v, v, q);
    }
    __shared__ float ss[256], qq[256];
    ss[threadIdx.x] = s; qq[threadIdx.x] = q;
    __syncthreads();
    if (rg == 0) {
        atomicAdd(&g_bnsum[c], s + ss[128 + c]);
        atomicAdd(&g_bnsq[c],  q + qq[128 + c]);
    }
}

// ============ kernel 5: fold stats into per-channel scale/shift ==============
__global__ void k_bnfinal(const float* __restrict__ gamma,
                          const float* __restrict__ beta)
{
    int c = threadIdx.x;                      // 128
    float mean = g_bnsum[c] * (1.f / NPROT);
    float var  = g_bnsq[c] * (1.f / NPROT) - mean * mean;
    float sc = gamma[c] * rsqrtf(var + 1e-5f);
    g_scale[c] = sc;
    g_shift[c] = beta[c] - mean * sc;
}

// ============ kernel 6: apply + leakyrelu (float4) ===========================
__global__ __launch_bounds__(256) void k_bnapply(float* __restrict__ out)
{
    int idx = blockIdx.x * 256 + threadIdx.x;     // NPROT*128/4 float4s
    int c = (idx * 4) & 127;
    float4 v  = ((const float4*)g_hp)[idx];
    float4 sc = *(const float4*)&g_scale[c];
    float4 sh = *(const float4*)&g_shift[c];
    float4 o;
    o.x = fmaf(v.x, sc.x, sh.x); o.x = (o.x > 0.f) ? o.x : ALPHA * o.x;
    o.y = fmaf(v.y, sc.y, sh.y); o.y = (o.y > 0.f) ? o.y : ALPHA * o.y;
    o.z = fmaf(v.z, sc.z, sh.z); o.z = (o.z > 0.f) ? o.z : ALPHA * o.z;
    o.w = fmaf(v.w, sc.w, sh.w); o.w = (o.w > 0.f) ? o.w : ALPHA * o.w;
    ((float4*)out)[idx] = o;
}

// ============ launch ==========================================================
extern "C" void kernel_launch(void* const* d_in, const int* in_sizes, int n_in,
                              void* d_out, int out_size)
{
    const float* h     = (const float*)d_in[0];
    const float* adj   = (const float*)d_in[1];
    const float* W1    = (const float*)d_in[2];
    const float* W2    = (const float*)d_in[3];
    const float* a     = (const float*)d_in[4];
    const float* gamma = (const float*)d_in[5];
    const float* beta  = (const float*)d_in[6];
    float* out = (float*)d_out;

    k_wh        <<<NPROT / 16, 256>>>(h, W1, W2, a);
    k_packattn1 <<<NPROT, 256>>>(adj);
    k_adj2attn2 <<<NPROT, 256>>>();
    k_bnstats   <<<NPROT / 32, 256>>>();
    k_bnfinal   <<<1, 128>>>(gamma, beta);
    k_bnapply   <<<(NPROT * 128 / 4) / 256, 256>>>(out);
}